// round 6
// baseline (speedup 1.0000x reference)
#include <cuda_runtime.h>
#include <cuda_fp16.h>
#include <cstdint>

// Problem constants
#define NA 4096
#define NB 4096
#define DD 256
#define HH 4
#define DK 64

// Scratch: projected Q/K/V in fp16 — __device__ globals (no allocs allowed)
__device__ __half g_Q[NA * DD];
__device__ __half g_K[NB * DD];
__device__ __half g_V[NB * DD];

__device__ __forceinline__ void mma16816(float c[4], const uint32_t a[4],
                                         uint32_t b0, uint32_t b1) {
    asm volatile(
        "mma.sync.aligned.m16n8k16.row.col.f32.f16.f16.f32 "
        "{%0,%1,%2,%3}, {%4,%5,%6,%7}, {%8,%9}, {%0,%1,%2,%3};\n"
        : "+f"(c[0]), "+f"(c[1]), "+f"(c[2]), "+f"(c[3])
        : "r"(a[0]), "r"(a[1]), "r"(a[2]), "r"(a[3]), "r"(b0), "r"(b1));
}

__device__ __forceinline__ uint32_t packh2(float x, float y) {
    __half2 t = __floats2half2_rn(x, y);
    return *reinterpret_cast<uint32_t*>(&t);
}

__device__ __forceinline__ void ldsm4(uint32_t r[4], const __half* p) {
    uint32_t a = (uint32_t)__cvta_generic_to_shared(p);
    asm volatile("ldmatrix.sync.aligned.m8n8.x4.shared.b16 {%0,%1,%2,%3}, [%4];\n"
                 : "=r"(r[0]), "=r"(r[1]), "=r"(r[2]), "=r"(r[3]) : "r"(a));
}

__device__ __forceinline__ void ldsm4t(uint32_t r[4], const __half* p) {
    uint32_t a = (uint32_t)__cvta_generic_to_shared(p);
    asm volatile("ldmatrix.sync.aligned.m8n8.x4.trans.shared.b16 {%0,%1,%2,%3}, [%4];\n"
                 : "=r"(r[0]), "=r"(r[1]), "=r"(r[2]), "=r"(r[3]) : "r"(a));
}

__device__ __forceinline__ void cpasync16(void* s, const void* g) {
    uint32_t sa = (uint32_t)__cvta_generic_to_shared(s);
    asm volatile("cp.async.cg.shared.global [%0], [%1], 16;\n" :: "r"(sa), "l"(g));
}
__device__ __forceinline__ void cp_commit() { asm volatile("cp.async.commit_group;\n"); }
__device__ __forceinline__ void cp_wait0() { asm volatile("cp.async.wait_group 0;\n" ::: "memory"); }

// ---------------------------------------------------------------------------
// Kernel 1: projections  Y = X @ W^T  (fp32 in, fp16 out), 3 GEMMs via grid.z
// ---------------------------------------------------------------------------
__global__ __launch_bounds__(128) void proj_kernel(
    const float* __restrict__ a_z, const float* __restrict__ bv_z,
    const float* __restrict__ Wq, const float* __restrict__ Wk,
    const float* __restrict__ Wv) {
    const float* X;
    const float* W;
    __half* Y;
    int z = blockIdx.z;
    if (z == 0)      { X = a_z;  W = Wq; Y = g_Q; }
    else if (z == 1) { X = bv_z; W = Wk; Y = g_K; }
    else             { X = bv_z; W = Wv; Y = g_V; }

    const int a0 = blockIdx.x * 64;
    const int n0 = blockIdx.y * 64;

    __shared__ __half sA[64][24];
    __shared__ __half sB[64][24];

    const int tid = threadIdx.x;
    const int lane = tid & 31, warp = tid >> 5;
    const int gr = lane >> 2, tig = lane & 3;
    const int wm = warp >> 1, wn = warp & 1;

    float acc[2][4][4] = {};

    for (int kt = 0; kt < DD / 16; kt++) {
        __syncthreads();
#pragma unroll
        for (int i = 0; i < 2; i++) {
            int j = tid + i * 128;
            int row = j >> 2, c4 = (j & 3) * 4;
            float4 xa = *(const float4*)&X[(size_t)(a0 + row) * DD + kt * 16 + c4];
            *(__half2*)&sA[row][c4]     = __floats2half2_rn(xa.x, xa.y);
            *(__half2*)&sA[row][c4 + 2] = __floats2half2_rn(xa.z, xa.w);
            float4 xb = *(const float4*)&W[(size_t)(n0 + row) * DD + kt * 16 + c4];
            *(__half2*)&sB[row][c4]     = __floats2half2_rn(xb.x, xb.y);
            *(__half2*)&sB[row][c4 + 2] = __floats2half2_rn(xb.z, xb.w);
        }
        __syncthreads();

        uint32_t af[2][4];
#pragma unroll
        for (int mt = 0; mt < 2; mt++) {
            const __half* p = &sA[wm * 32 + mt * 16 + gr][tig * 2];
            af[mt][0] = *(const uint32_t*)p;
            af[mt][1] = *(const uint32_t*)(p + 8 * 24);
            af[mt][2] = *(const uint32_t*)(p + 8);
            af[mt][3] = *(const uint32_t*)(p + 8 * 24 + 8);
        }
#pragma unroll
        for (int nt = 0; nt < 4; nt++) {
            const __half* p = &sB[wn * 32 + nt * 8 + gr][tig * 2];
            uint32_t b0 = *(const uint32_t*)p;
            uint32_t b1 = *(const uint32_t*)(p + 8);
            mma16816(acc[0][nt], af[0], b0, b1);
            mma16816(acc[1][nt], af[1], b0, b1);
        }
    }

#pragma unroll
    for (int mt = 0; mt < 2; mt++)
#pragma unroll
        for (int nt = 0; nt < 4; nt++) {
            int row = a0 + wm * 32 + mt * 16 + gr;
            int col = n0 + wn * 32 + nt * 8 + tig * 2;
            *(__half2*)&Y[(size_t)row * DD + col] = __floats2half2_rn(acc[mt][nt][0], acc[mt][nt][1]);
            *(__half2*)&Y[(size_t)(row + 8) * DD + col] = __floats2half2_rn(acc[mt][nt][2], acc[mt][nt][3]);
        }
}

// ---------------------------------------------------------------------------
// Kernel 2: fused attention v3.
// 128 CTAs x 512 threads (16 warps). warp = (head h=w&3, m-half mh=(w>>2)&1,
// b-half bh=w>>3). Each warp: 16x16 S sub-tile, partial PV numerator + den over
// its b-half; partials summed in smem at the end (additive — no online softmax
// needed since logits are clipped to [-10,10]).
// ---------------------------------------------------------------------------
#define KSTRIDE 264                      // halves per K/V row (512B data + 16B pad)
#define KBUF_HALVES (32 * KSTRIDE)       // 8448 halves = 16896 B
#define WSTRIDE 36                       // floats per sW row

#define OFF_V (2 * KBUF_HALVES * 2)      // 33792 B
#define OFF_W (OFF_V + 2 * KBUF_HALVES * 2)  // 67584 B
#define SMEM_TOTAL (OFF_W + 2 * 32 * WSTRIDE * 4)  // 67584 + 9216 = 76800 B

// final-reduction smem reuse: ctx[2 bh][4 h][32 rows][68] + den_s[2][4][32]
#define CTX_FLOATS (2 * 4 * 32 * 68)     // 17408 floats = 69632 B
// CTX_FLOATS*4 + 1024 = 70656 <= 76800 OK

#define ONESH2 0x3C003C00u               // half2 {1.0, 1.0}

__global__ __launch_bounds__(512) void attn_kernel(
    const int* __restrict__ mask, const float* __restrict__ weight,
    float* __restrict__ out) {
    extern __shared__ __align__(16) unsigned char smem[];
    __half* sK = reinterpret_cast<__half*>(smem);
    __half* sV = reinterpret_cast<__half*>(smem + OFF_V);
    float*  sW = reinterpret_cast<float*>(smem + OFF_W);

    const int tid = threadIdx.x;
    const int lane = tid & 31;
    const int w = tid >> 5;
    const int h = w & 3;                 // head
    const int mh = (w >> 2) & 1;         // m-half: a-rows mh*16..+15
    const int bh = w >> 3;               // b-half: tile cols bh*16..+15
    const int gr = lane >> 2, tig = lane & 3;
    const int a0 = blockIdx.x * 32;

    // Q fragments (16 rows, 4 k-steps of 16)
    uint32_t qf[4][4];
#pragma unroll
    for (int ks = 0; ks < 4; ks++) {
        const __half* q = &g_Q[(size_t)(a0 + mh * 16 + gr) * DD + h * DK + ks * 16 + tig * 2];
        qf[ks][0] = *(const uint32_t*)q;
        qf[ks][1] = *(const uint32_t*)(q + 8 * DD);
        qf[ks][2] = *(const uint32_t*)(q + 8);
        qf[ks][3] = *(const uint32_t*)(q + 8 * DD + 8);
    }

    float cacc[8][4] = {};   // partial context numerator (this b-half): 8 d-blocks
    float denacc[4] = {};    // partial den via MMA-ones

    // W/mask fold geometry: threads 0..255 each own one float4 of the 32x32 tile
    const int wrow = tid >> 3, wc4 = (tid & 7) * 4;
    const bool wldr = tid < 256;

    // ---- prologue: stage tile 0 ----
    {
#pragma unroll
        for (int i = 0; i < 2; i++) {
            int j = tid + i * 512;
            int row = j >> 5, ch = (j & 31) * 8;
            cpasync16(&sK[row * KSTRIDE + ch], &g_K[(size_t)row * DD + ch]);
            cpasync16(&sV[row * KSTRIDE + ch], &g_V[(size_t)row * DD + ch]);
        }
        cp_commit();
        if (wldr) {
            float4 w4 = *(const float4*)&weight[(size_t)(a0 + wrow) * NB + wc4];
            int4   m4 = *(const int4*)&mask[(size_t)(a0 + wrow) * NB + wc4];
            float4 f;
            f.x = m4.x ? w4.x : -1e30f;
            f.y = m4.y ? w4.y : -1e30f;
            f.z = m4.z ? w4.z : -1e30f;
            f.w = m4.w ? w4.w : -1e30f;
            *(float4*)&sW[wrow * WSTRIDE + wc4] = f;
        }
    }

    for (int t = 0; t < NB / 32; t++) {
        cp_wait0();
        __syncthreads();

        const int buf = t & 1;
        const __half* kb = sK + buf * KBUF_HALVES;
        const __half* vb = sV + buf * KBUF_HALVES;
        const float*  wb = sW + buf * 32 * WSTRIDE;

        // ---- prefetch tile t+1 ----
        float4 wreg; int4 mreg;
        const bool pre = (t + 1) < NB / 32;
        if (pre) {
            const int b1 = (t + 1) * 32;
            __half* kn = sK + ((t + 1) & 1) * KBUF_HALVES;
            __half* vn = sV + ((t + 1) & 1) * KBUF_HALVES;
#pragma unroll
            for (int i = 0; i < 2; i++) {
                int j = tid + i * 512;
                int row = j >> 5, ch = (j & 31) * 8;
                cpasync16(&kn[row * KSTRIDE + ch], &g_K[(size_t)(b1 + row) * DD + ch]);
                cpasync16(&vn[row * KSTRIDE + ch], &g_V[(size_t)(b1 + row) * DD + ch]);
            }
            cp_commit();
            if (wldr) {
                wreg = *(const float4*)&weight[(size_t)(a0 + wrow) * NB + b1 + wc4];
                mreg = *(const int4*)&mask[(size_t)(a0 + wrow) * NB + b1 + wc4];
            }
        }

        // ---- S = Q K^T (16 x 16 per warp: this b-half) ----
        float sacc[2][4] = {};
#pragma unroll
        for (int nt = 0; nt < 2; nt++) {
            uint32_t kf[8];
            const __half* p1 = &kb[(bh * 16 + nt * 8 + (lane & 7)) * KSTRIDE + h * DK + (lane >> 3) * 8];
            ldsm4(kf, p1);
            ldsm4(kf + 4, p1 + 32);
            mma16816(sacc[nt], qf[0], kf[0], kf[1]);
            mma16816(sacc[nt], qf[1], kf[2], kf[3]);
            mma16816(sacc[nt], qf[2], kf[4], kf[5]);
            mma16816(sacc[nt], qf[3], kf[6], kf[7]);
        }

        // ---- epilogue: p = exp(clip(s/8 + w', -10, 10)); pack 16x16 A-frag ----
        uint32_t pa[4];
#pragma unroll
        for (int nt = 0; nt < 2; nt++) {
            const float* wp0 = &wb[(mh * 16 + gr) * WSTRIDE + bh * 16 + nt * 8 + tig * 2];
            float2 w0 = *(const float2*)wp0;
            float2 w1 = *(const float2*)(wp0 + 8 * WSTRIDE);
            float p0 = __expf(fmaxf(fminf(sacc[nt][0] * 0.125f + w0.x, 10.f), -10.f));
            float p1 = __expf(fmaxf(fminf(sacc[nt][1] * 0.125f + w0.y, 10.f), -10.f));
            float p2 = __expf(fmaxf(fminf(sacc[nt][2] * 0.125f + w1.x, 10.f), -10.f));
            float p3 = __expf(fmaxf(fminf(sacc[nt][3] * 0.125f + w1.y, 10.f), -10.f));
            pa[nt * 2 + 0] = packh2(p0, p1);
            pa[nt * 2 + 1] = packh2(p2, p3);
        }

        // ---- den partial += P @ ones ----
        mma16816(denacc, pa, ONESH2, ONESH2);

        // ---- context partial += P @ V ----
        // One ldsm4t covers two d-blocks: m0/m1 = k rows (bh half), n-cols c..c+7;
        // m2/m3 = n-cols c+8..c+15.
        const int g = lane >> 3, r = lane & 7;
#pragma unroll
        for (int pr = 0; pr < 4; pr++) {
            uint32_t vf[4];
            const __half* vp = &vb[(bh * 16 + (g & 1) * 8 + r) * KSTRIDE + h * DK + pr * 16 + (g >> 1) * 8];
            ldsm4t(vf, vp);
            mma16816(cacc[pr * 2 + 0], pa, vf[0], vf[1]);
            mma16816(cacc[pr * 2 + 1], pa, vf[2], vf[3]);
        }

        // ---- store folded W for tile t+1 ----
        if (pre && wldr) {
            float4 f;
            f.x = mreg.x ? wreg.x : -1e30f;
            f.y = mreg.y ? wreg.y : -1e30f;
            f.z = mreg.z ? wreg.z : -1e30f;
            f.w = mreg.w ? wreg.w : -1e30f;
            *(float4*)&sW[((t + 1) & 1) * 32 * WSTRIDE + wrow * WSTRIDE + wc4] = f;
        }
    }

    __syncthreads();  // staging smem dead; reuse for partial reduction
    float* ctx   = reinterpret_cast<float*>(smem);          // [2][4][32][68]
    float* den_s = reinterpret_cast<float*>(smem) + CTX_FLOATS;  // [2][4][32]

    // write unnormalized partial numerators
#pragma unroll
    for (int nt2 = 0; nt2 < 8; nt2++) {
        size_t r0 = ((size_t)(bh * 4 + h) * 32 + mh * 16 + gr) * 68 + nt2 * 8 + tig * 2;
        ctx[r0]          = cacc[nt2][0];
        ctx[r0 + 1]      = cacc[nt2][1];
        ctx[r0 + 8 * 68]     = cacc[nt2][2];
        ctx[r0 + 8 * 68 + 1] = cacc[nt2][3];
    }
    // write partial denominators (all lanes in a row-group hold identical c[0]/c[2])
    if (tig == 0) {
        den_s[(bh * 4 + h) * 32 + mh * 16 + gr]     = denacc[0];
        den_s[(bh * 4 + h) * 32 + mh * 16 + gr + 8] = denacc[2];
    }
    __syncthreads();

    // topic_align = 0.25 * sum_h (num0+num1)/(den0+den1)
#pragma unroll
    for (int i = 0; i < 4; i++) {
        int e = tid + i * 512;
        int a = e >> 6, dc = e & 63;
        float acc = 0.f;
#pragma unroll
        for (int hh = 0; hh < 4; hh++) {
            float num = ctx[((size_t)hh * 32 + a) * 68 + dc] +
                        ctx[((size_t)(4 + hh) * 32 + a) * 68 + dc];
            float den = den_s[hh * 32 + a] + den_s[(4 + hh) * 32 + a];
            acc += num / den;
        }
        out[(size_t)(a0 + a) * DK + dc] = 0.25f * acc;
    }
    // influence = mean_h(sum_b softmax) == 1.0 (ref deviates only by fp roundoff)
    if (tid < 32) out[(size_t)NA * DK + a0 + tid] = 1.0f;
}

// ---------------------------------------------------------------------------
// Launch: inputs (metadata order): a_z, bv_z, mask(bool->int32), weight, Wq, Wk, Wv, h
// ---------------------------------------------------------------------------
extern "C" void kernel_launch(void* const* d_in, const int* in_sizes, int n_in,
                              void* d_out, int out_size) {
    const float* a_z  = (const float*)d_in[0];
    const float* bv_z = (const float*)d_in[1];
    const int*   mask = (const int*)d_in[2];
    const float* weight = (const float*)d_in[3];
    const float* Wq = (const float*)d_in[4];
    const float* Wk = (const float*)d_in[5];
    const float* Wv = (const float*)d_in[6];
    float* out = (float*)d_out;

    cudaFuncSetAttribute(attn_kernel, cudaFuncAttributeMaxDynamicSharedMemorySize, SMEM_TOTAL);

    dim3 pg(NA / 64, DD / 64, 3);
    proj_kernel<<<pg, 128>>>(a_z, bv_z, Wq, Wk, Wv);
    attn_kernel<<<NA / 32, 512, SMEM_TOTAL>>>(mask, weight, out);
}

// round 7
// speedup vs baseline: 1.8888x; 1.8888x over previous
#include <cuda_runtime.h>
#include <cuda_fp16.h>
#include <cstdint>

// Problem constants
#define NA 4096
#define NB 4096
#define DD 256
#define HH 4
#define DK 64
#define BSPLIT 2
#define NB_HALF (NB / BSPLIT)

// Scratch: projected Q/K/V in fp16 + partial accumulators — __device__ globals
__device__ __half g_Q[NA * DD];
__device__ __half g_K[NB * DD];
__device__ __half g_V[NB * DD];
__device__ float g_num[BSPLIT][NA][HH][DK];  // 8 MB partial numerators
__device__ float g_den[BSPLIT][NA][HH];      // partial denominators

__device__ __forceinline__ void mma16816(float c[4], const uint32_t a[4],
                                         uint32_t b0, uint32_t b1) {
    asm volatile(
        "mma.sync.aligned.m16n8k16.row.col.f32.f16.f16.f32 "
        "{%0,%1,%2,%3}, {%4,%5,%6,%7}, {%8,%9}, {%0,%1,%2,%3};\n"
        : "+f"(c[0]), "+f"(c[1]), "+f"(c[2]), "+f"(c[3])
        : "r"(a[0]), "r"(a[1]), "r"(a[2]), "r"(a[3]), "r"(b0), "r"(b1));
}

__device__ __forceinline__ uint32_t packh2(float x, float y) {
    __half2 t = __floats2half2_rn(x, y);
    return *reinterpret_cast<uint32_t*>(&t);
}

__device__ __forceinline__ void ldsm4(uint32_t r[4], const __half* p) {
    uint32_t a = (uint32_t)__cvta_generic_to_shared(p);
    asm volatile("ldmatrix.sync.aligned.m8n8.x4.shared.b16 {%0,%1,%2,%3}, [%4];\n"
                 : "=r"(r[0]), "=r"(r[1]), "=r"(r[2]), "=r"(r[3]) : "r"(a));
}

__device__ __forceinline__ void ldsm4t(uint32_t r[4], const __half* p) {
    uint32_t a = (uint32_t)__cvta_generic_to_shared(p);
    asm volatile("ldmatrix.sync.aligned.m8n8.x4.trans.shared.b16 {%0,%1,%2,%3}, [%4];\n"
                 : "=r"(r[0]), "=r"(r[1]), "=r"(r[2]), "=r"(r[3]) : "r"(a));
}

__device__ __forceinline__ void cpasync16(void* s, const void* g) {
    uint32_t sa = (uint32_t)__cvta_generic_to_shared(s);
    asm volatile("cp.async.cg.shared.global [%0], [%1], 16;\n" :: "r"(sa), "l"(g));
}
__device__ __forceinline__ void cp_commit() { asm volatile("cp.async.commit_group;\n"); }
__device__ __forceinline__ void cp_wait0() { asm volatile("cp.async.wait_group 0;\n" ::: "memory"); }

// ---------------------------------------------------------------------------
// Kernel 1: projections  Y = X @ W^T  (fp32 in, fp16 out), 3 GEMMs via grid.z
// ---------------------------------------------------------------------------
__global__ __launch_bounds__(128) void proj_kernel(
    const float* __restrict__ a_z, const float* __restrict__ bv_z,
    const float* __restrict__ Wq, const float* __restrict__ Wk,
    const float* __restrict__ Wv) {
    const float* X;
    const float* W;
    __half* Y;
    int z = blockIdx.z;
    if (z == 0)      { X = a_z;  W = Wq; Y = g_Q; }
    else if (z == 1) { X = bv_z; W = Wk; Y = g_K; }
    else             { X = bv_z; W = Wv; Y = g_V; }

    const int a0 = blockIdx.x * 64;
    const int n0 = blockIdx.y * 64;

    __shared__ __half sA[64][24];
    __shared__ __half sB[64][24];

    const int tid = threadIdx.x;
    const int lane = tid & 31, warp = tid >> 5;
    const int gr = lane >> 2, tig = lane & 3;
    const int wm = warp >> 1, wn = warp & 1;

    float acc[2][4][4] = {};

    for (int kt = 0; kt < DD / 16; kt++) {
        __syncthreads();
#pragma unroll
        for (int i = 0; i < 2; i++) {
            int j = tid + i * 128;
            int row = j >> 2, c4 = (j & 3) * 4;
            float4 xa = *(const float4*)&X[(size_t)(a0 + row) * DD + kt * 16 + c4];
            *(__half2*)&sA[row][c4]     = __floats2half2_rn(xa.x, xa.y);
            *(__half2*)&sA[row][c4 + 2] = __floats2half2_rn(xa.z, xa.w);
            float4 xb = *(const float4*)&W[(size_t)(n0 + row) * DD + kt * 16 + c4];
            *(__half2*)&sB[row][c4]     = __floats2half2_rn(xb.x, xb.y);
            *(__half2*)&sB[row][c4 + 2] = __floats2half2_rn(xb.z, xb.w);
        }
        __syncthreads();

        uint32_t af[2][4];
#pragma unroll
        for (int mt = 0; mt < 2; mt++) {
            const __half* p = &sA[wm * 32 + mt * 16 + gr][tig * 2];
            af[mt][0] = *(const uint32_t*)p;
            af[mt][1] = *(const uint32_t*)(p + 8 * 24);
            af[mt][2] = *(const uint32_t*)(p + 8);
            af[mt][3] = *(const uint32_t*)(p + 8 * 24 + 8);
        }
#pragma unroll
        for (int nt = 0; nt < 4; nt++) {
            const __half* p = &sB[wn * 32 + nt * 8 + gr][tig * 2];
            uint32_t b0 = *(const uint32_t*)p;
            uint32_t b1 = *(const uint32_t*)(p + 8);
            mma16816(acc[0][nt], af[0], b0, b1);
            mma16816(acc[1][nt], af[1], b0, b1);
        }
    }

#pragma unroll
    for (int mt = 0; mt < 2; mt++)
#pragma unroll
        for (int nt = 0; nt < 4; nt++) {
            int row = a0 + wm * 32 + mt * 16 + gr;
            int col = n0 + wn * 32 + nt * 8 + tig * 2;
            *(__half2*)&Y[(size_t)row * DD + col] = __floats2half2_rn(acc[mt][nt][0], acc[mt][nt][1]);
            *(__half2*)&Y[(size_t)(row + 8) * DD + col] = __floats2half2_rn(acc[mt][nt][2], acc[mt][nt][3]);
        }
}

// ---------------------------------------------------------------------------
// Kernel 2: fused attention v4 = v2 warp shape + b-split across CTAs.
// grid (128, 2): blockIdx.x = a-tile (BM=32), blockIdx.y = b-half.
// 256 threads, 8 warps: warp = (head h = w&3, m-half mh = w>>2), 16x32 S tile.
// Each CTA loops its 64 b-tiles, writes unnormalized partial num/den to global.
// ---------------------------------------------------------------------------
#define KSTRIDE 264                      // halves per K/V row (512B data + 16B pad)
#define KBUF_HALVES (32 * KSTRIDE)       // 16896 B
#define WSTRIDE 36                       // floats per sW row

#define OFF_V (2 * KBUF_HALVES * 2)      // 33792 B
#define OFF_W (OFF_V + 2 * KBUF_HALVES * 2)  // 67584 B
#define SMEM_TOTAL (OFF_W + 2 * 32 * WSTRIDE * 4)  // 76800 B  (2 CTAs/SM fit)

#define ONESH2 0x3C003C00u               // half2 {1.0, 1.0}

__global__ __launch_bounds__(256) void attn_kernel(
    const int* __restrict__ mask, const float* __restrict__ weight) {
    extern __shared__ __align__(16) unsigned char smem[];
    __half* sK = reinterpret_cast<__half*>(smem);
    __half* sV = reinterpret_cast<__half*>(smem + OFF_V);
    float*  sW = reinterpret_cast<float*>(smem + OFF_W);

    const int tid = threadIdx.x;
    const int lane = tid & 31;
    const int w = tid >> 5;
    const int h = w & 3;                 // head
    const int mh = w >> 2;               // m-half: rows mh*16..+15
    const int gr = lane >> 2, tig = lane & 3;
    const int a0 = blockIdx.x * 32;
    const int bh = blockIdx.y;
    const int bbase = bh * NB_HALF;

    // Q fragments (16 rows, 4 k-steps)
    uint32_t qf[4][4];
#pragma unroll
    for (int ks = 0; ks < 4; ks++) {
        const __half* q = &g_Q[(size_t)(a0 + mh * 16 + gr) * DD + h * DK + ks * 16 + tig * 2];
        qf[ks][0] = *(const uint32_t*)q;
        qf[ks][1] = *(const uint32_t*)(q + 8 * DD);
        qf[ks][2] = *(const uint32_t*)(q + 8);
        qf[ks][3] = *(const uint32_t*)(q + 8 * DD + 8);
    }

    float cacc[8][4] = {};   // partial context numerator
    float denacc[4] = {};    // partial den via MMA-ones

    const int wrow = tid >> 3, wc4 = (tid & 7) * 4;

    // ---- prologue: stage tile 0 ----
    {
#pragma unroll
        for (int i = 0; i < 4; i++) {
            int j = tid + i * 256;
            int row = j >> 5, ch = (j & 31) * 8;
            cpasync16(&sK[row * KSTRIDE + ch], &g_K[(size_t)(bbase + row) * DD + ch]);
            cpasync16(&sV[row * KSTRIDE + ch], &g_V[(size_t)(bbase + row) * DD + ch]);
        }
        cp_commit();
        float4 w4 = *(const float4*)&weight[(size_t)(a0 + wrow) * NB + bbase + wc4];
        int4   m4 = *(const int4*)&mask[(size_t)(a0 + wrow) * NB + bbase + wc4];
        float4 f;
        f.x = m4.x ? w4.x : -1e30f;
        f.y = m4.y ? w4.y : -1e30f;
        f.z = m4.z ? w4.z : -1e30f;
        f.w = m4.w ? w4.w : -1e30f;
        *(float4*)&sW[wrow * WSTRIDE + wc4] = f;
    }

    for (int t = 0; t < NB_HALF / 32; t++) {
        cp_wait0();
        __syncthreads();

        const int buf = t & 1;
        const __half* kb = sK + buf * KBUF_HALVES;
        const __half* vb = sV + buf * KBUF_HALVES;
        const float*  wb = sW + buf * 32 * WSTRIDE;

        // ---- prefetch tile t+1 ----
        float4 wreg; int4 mreg;
        const bool pre = (t + 1) < NB_HALF / 32;
        if (pre) {
            const int b1 = bbase + (t + 1) * 32;
            __half* kn = sK + ((t + 1) & 1) * KBUF_HALVES;
            __half* vn = sV + ((t + 1) & 1) * KBUF_HALVES;
#pragma unroll
            for (int i = 0; i < 4; i++) {
                int j = tid + i * 256;
                int row = j >> 5, ch = (j & 31) * 8;
                cpasync16(&kn[row * KSTRIDE + ch], &g_K[(size_t)(b1 + row) * DD + ch]);
                cpasync16(&vn[row * KSTRIDE + ch], &g_V[(size_t)(b1 + row) * DD + ch]);
            }
            cp_commit();
            wreg = *(const float4*)&weight[(size_t)(a0 + wrow) * NB + b1 + wc4];
            mreg = *(const int4*)&mask[(size_t)(a0 + wrow) * NB + b1 + wc4];
        }

        // ---- S = Q K^T (16 x 32 per warp) ----
        float sacc[4][4] = {};
#pragma unroll
        for (int nt = 0; nt < 4; nt++) {
            uint32_t kf[8];
            const __half* p1 = &kb[(nt * 8 + (lane & 7)) * KSTRIDE + h * DK + (lane >> 3) * 8];
            ldsm4(kf, p1);
            ldsm4(kf + 4, p1 + 32);
            mma16816(sacc[nt], qf[0], kf[0], kf[1]);
            mma16816(sacc[nt], qf[1], kf[2], kf[3]);
            mma16816(sacc[nt], qf[2], kf[4], kf[5]);
            mma16816(sacc[nt], qf[3], kf[6], kf[7]);
        }

        // ---- p = exp(clip(s/8 + w', -10, 10)); pack as A-frag ----
        uint32_t pa[2][4];
#pragma unroll
        for (int nt = 0; nt < 4; nt++) {
            const float* wp0 = &wb[(mh * 16 + gr) * WSTRIDE + nt * 8 + tig * 2];
            float2 w0 = *(const float2*)wp0;
            float2 w1 = *(const float2*)(wp0 + 8 * WSTRIDE);
            float p0 = __expf(fmaxf(fminf(sacc[nt][0] * 0.125f + w0.x, 10.f), -10.f));
            float p1 = __expf(fmaxf(fminf(sacc[nt][1] * 0.125f + w0.y, 10.f), -10.f));
            float p2 = __expf(fmaxf(fminf(sacc[nt][2] * 0.125f + w1.x, 10.f), -10.f));
            float p3 = __expf(fmaxf(fminf(sacc[nt][3] * 0.125f + w1.y, 10.f), -10.f));
            int kk = nt >> 1, hf = nt & 1;
            pa[kk][hf * 2 + 0] = packh2(p0, p1);
            pa[kk][hf * 2 + 1] = packh2(p2, p3);
        }

        // ---- den partial += P @ ones ----
        mma16816(denacc, pa[0], ONESH2, ONESH2);
        mma16816(denacc, pa[1], ONESH2, ONESH2);

        // ---- context partial += P @ V ----
#pragma unroll
        for (int nt2 = 0; nt2 < 8; nt2++) {
            uint32_t vf[4];
            ldsm4t(vf, &vb[lane * KSTRIDE + h * DK + nt2 * 8]);
            mma16816(cacc[nt2], pa[0], vf[0], vf[1]);
            mma16816(cacc[nt2], pa[1], vf[2], vf[3]);
        }

        // ---- store folded W for tile t+1 ----
        if (pre) {
            float4 f;
            f.x = mreg.x ? wreg.x : -1e30f;
            f.y = mreg.y ? wreg.y : -1e30f;
            f.z = mreg.z ? wreg.z : -1e30f;
            f.w = mreg.w ? wreg.w : -1e30f;
            *(float4*)&sW[((t + 1) & 1) * 32 * WSTRIDE + wrow * WSTRIDE + wc4] = f;
        }
    }

    // ---- write partial numerators + denominators to global scratch ----
    const int r0 = a0 + mh * 16 + gr;
#pragma unroll
    for (int nt2 = 0; nt2 < 8; nt2++) {
        int dc = nt2 * 8 + tig * 2;
        *(float2*)&g_num[bh][r0][h][dc]     = make_float2(cacc[nt2][0], cacc[nt2][1]);
        *(float2*)&g_num[bh][r0 + 8][h][dc] = make_float2(cacc[nt2][2], cacc[nt2][3]);
    }
    if (tig == 0) {
        g_den[bh][r0][h]     = denacc[0];
        g_den[bh][r0 + 8][h] = denacc[2];
    }
}

// ---------------------------------------------------------------------------
// Kernel 3: combine b-half partials, normalize, mean over heads; influence=1.
// ---------------------------------------------------------------------------
__global__ __launch_bounds__(256) void reduce_kernel(float* __restrict__ out) {
    int idx = blockIdx.x * 256 + threadIdx.x;   // 0 .. NA*DK-1
    int a = idx >> 6, dc = idx & 63;
    float acc = 0.f;
#pragma unroll
    for (int h = 0; h < HH; h++) {
        float num = g_num[0][a][h][dc] + g_num[1][a][h][dc];
        float den = g_den[0][a][h] + g_den[1][a][h];
        acc += num / den;
    }
    out[idx] = 0.25f * acc;
    if (idx < NA) out[NA * DK + idx] = 1.0f;  // influence == 1.0 up to fp roundoff
}

// ---------------------------------------------------------------------------
// Launch: inputs (metadata order): a_z, bv_z, mask(bool->int32), weight, Wq, Wk, Wv, h
// ---------------------------------------------------------------------------
extern "C" void kernel_launch(void* const* d_in, const int* in_sizes, int n_in,
                              void* d_out, int out_size) {
    const float* a_z  = (const float*)d_in[0];
    const float* bv_z = (const float*)d_in[1];
    const int*   mask = (const int*)d_in[2];
    const float* weight = (const float*)d_in[3];
    const float* Wq = (const float*)d_in[4];
    const float* Wk = (const float*)d_in[5];
    const float* Wv = (const float*)d_in[6];
    float* out = (float*)d_out;

    cudaFuncSetAttribute(attn_kernel, cudaFuncAttributeMaxDynamicSharedMemorySize, SMEM_TOTAL);

    dim3 pg(NA / 64, DD / 64, 3);
    proj_kernel<<<pg, 128>>>(a_z, bv_z, Wq, Wk, Wv);
    attn_kernel<<<dim3(NA / 32, BSPLIT), 256, SMEM_TOTAL>>>(mask, weight);
    reduce_kernel<<<(NA * DK) / 256, 256>>>(out);
}